// round 2
// baseline (speedup 1.0000x reference)
#include <cuda_runtime.h>

// ---------------- problem constants ----------------
#define S_LEN 2048
#define B_SZ  2
#define NHEAD 16
#define DHEAD 128
#define HIDN  2048
#define QKVN  6144               // 3*NHEAD*DHEAD
#define MROWS (S_LEN * B_SZ)     // 4096
#define SCALE 0.08838834764831845f  // 1/sqrt(128)

static __device__ __forceinline__ float neg_inf() { return __int_as_float(0xff800000); }

// ---------------- scratch (static device globals; no allocations) ----------------
__device__ float g_q[(size_t)B_SZ * NHEAD * S_LEN * DHEAD];   // [B,NH,S,DH]
__device__ float g_k[(size_t)B_SZ * NHEAD * S_LEN * DHEAD];
__device__ float g_v[(size_t)B_SZ * NHEAD * S_LEN * DHEAD];
__device__ float g_ctx[(size_t)MROWS * HIDN];                 // [s*B+b, NH*DH]

// ============================================================================
// Kernel 1: QKV GEMM  mixed[4096,6144] = hidden[4096,2048] @ Wqkv + b
// 128x128 tile, TK=16, 256 threads, 8x8 microtile (2x2 blocks of 4x4).
// Epilogue scatters into g_q / g_k / g_v with Megatron per-head layout.
// ============================================================================
__global__ __launch_bounds__(256) void qkv_gemm_kernel(
    const float* __restrict__ A, const float* __restrict__ W,
    const float* __restrict__ bias)
{
    __shared__ float As[16][132];   // transposed: As[kk][row]
    __shared__ float Bs[16][132];   // Bs[kk][col]

    const int tid = threadIdx.x;
    const int rowBase = blockIdx.y * 128;
    const int colBase = blockIdx.x * 128;
    const int tx = tid & 15, ty = tid >> 4;

    float acc[8][8];
#pragma unroll
    for (int i = 0; i < 8; i++)
#pragma unroll
        for (int j = 0; j < 8; j++) acc[i][j] = 0.f;

    const int lrow = tid >> 2;          // 0..63
    const int lk   = (tid & 3) * 4;     // 0,4,8,12
    const int bkr  = tid >> 5;          // 0..7
    const int bcol = (tid & 31) * 4;    // 0..124

    for (int k0 = 0; k0 < HIDN; k0 += 16) {
#pragma unroll
        for (int h = 0; h < 2; h++) {
            int r = lrow + h * 64;
            float4 av = *(const float4*)(A + (size_t)(rowBase + r) * HIDN + k0 + lk);
            As[lk + 0][r] = av.x; As[lk + 1][r] = av.y;
            As[lk + 2][r] = av.z; As[lk + 3][r] = av.w;
        }
#pragma unroll
        for (int h = 0; h < 2; h++) {
            int kr = bkr + h * 8;
            float4 bv = *(const float4*)(W + (size_t)(k0 + kr) * QKVN + colBase + bcol);
            *(float4*)&Bs[kr][bcol] = bv;
        }
        __syncthreads();
#pragma unroll
        for (int kk = 0; kk < 16; kk++) {
            float4 a0 = *(const float4*)&As[kk][ty * 4];
            float4 a1 = *(const float4*)&As[kk][64 + ty * 4];
            float4 b0 = *(const float4*)&Bs[kk][tx * 4];
            float4 b1 = *(const float4*)&Bs[kk][64 + tx * 4];
            float ar[8] = {a0.x, a0.y, a0.z, a0.w, a1.x, a1.y, a1.z, a1.w};
            float br[8] = {b0.x, b0.y, b0.z, b0.w, b1.x, b1.y, b1.z, b1.w};
#pragma unroll
            for (int i = 0; i < 8; i++)
#pragma unroll
                for (int j = 0; j < 8; j++)
                    acc[i][j] = fmaf(ar[i], br[j], acc[i][j]);
        }
        __syncthreads();
    }

    // epilogue: scatter to q/k/v  (col c: head=c/384, j=c%384, which=j/128, d=j%128)
#pragma unroll
    for (int i = 0; i < 8; i++) {
        int r = rowBase + ((i < 4) ? (ty * 4 + i) : (64 + ty * 4 + i - 4));
        int s = r >> 1;          // B_SZ = 2
        int b = r & 1;
#pragma unroll
        for (int j = 0; j < 8; j++) {
            int c = colBase + ((j < 4) ? (tx * 4 + j) : (64 + tx * 4 + j - 4));
            float v = acc[i][j] + bias[c];
            int head  = c / 384;
            int jj    = c - head * 384;
            int which = jj >> 7;
            int d     = jj & 127;
            float* dst = (which == 0) ? g_q : (which == 1) ? g_k : g_v;
            dst[(((size_t)b * NHEAD + head) * S_LEN + s) * DHEAD + d] = v;
        }
    }
}

// ============================================================================
// Kernel 2: flash-style causal attention. grid (S/64, B*NH), 256 threads.
// Qs/Ks stored transposed [d][row] for vectorized score phase.
// ============================================================================
#define BQ 64
#define BK 64
#define QPAD 68
#define ATTN_SMEM_BYTES ((2 * 128 * QPAD + 64 * 128 + 64 * QPAD + 3 * 64) * 4)

__global__ __launch_bounds__(256) void attn_kernel()
{
    extern __shared__ float sm[];
    float* Qs    = sm;                       // [128][68]
    float* Ks    = sm + 128 * QPAD;          // [128][68]
    float* Vs    = sm + 2 * 128 * QPAD;      // [64][128]
    float* Ps    = Vs + 64 * 128;            // [64][68]
    float* rowm  = Ps + 64 * QPAD;
    float* rowl  = rowm + 64;
    float* rowsc = rowl + 64;

    const int tid = threadIdx.x;
    const int qb  = blockIdx.x;
    const int bh  = blockIdx.y;              // b*NH + h
    const int qBase = qb * BQ;
    const size_t base = (size_t)bh * S_LEN * DHEAD;

    const int tx = tid & 15;
    const int ty = tid >> 4;
    const int r0 = ty * 4;

    // load Q tile transposed
    for (int f = tid; f < BQ * DHEAD / 4; f += 256) {
        int row = f >> 5;
        int d4  = (f & 31) * 4;
        float4 v = *(const float4*)(g_q + base + (size_t)(qBase + row) * DHEAD + d4);
        Qs[(d4 + 0) * QPAD + row] = v.x;
        Qs[(d4 + 1) * QPAD + row] = v.y;
        Qs[(d4 + 2) * QPAD + row] = v.z;
        Qs[(d4 + 3) * QPAD + row] = v.w;
    }
    if (tid < 64) { rowm[tid] = neg_inf(); rowl[tid] = 0.f; }

    float o[4][8];
#pragma unroll
    for (int i = 0; i < 4; i++)
#pragma unroll
        for (int j = 0; j < 8; j++) o[i][j] = 0.f;

    for (int kb = 0; kb <= qb; kb++) {
        const int kBase = kb * BK;
        __syncthreads();   // protect Ks/Vs/Ps from previous iteration's readers
        for (int f = tid; f < BK * DHEAD / 4; f += 256) {
            int row = f >> 5;
            int d4  = (f & 31) * 4;
            float4 kv = *(const float4*)(g_k + base + (size_t)(kBase + row) * DHEAD + d4);
            Ks[(d4 + 0) * QPAD + row] = kv.x;
            Ks[(d4 + 1) * QPAD + row] = kv.y;
            Ks[(d4 + 2) * QPAD + row] = kv.z;
            Ks[(d4 + 3) * QPAD + row] = kv.w;
            float4 vv = *(const float4*)(g_v + base + (size_t)(kBase + row) * DHEAD + d4);
            *(float4*)&Vs[row * 128 + d4] = vv;
        }
        __syncthreads();

        // scores: 4x4 per thread over DH=128
        float sc[4][4];
#pragma unroll
        for (int i = 0; i < 4; i++)
#pragma unroll
            for (int j = 0; j < 4; j++) sc[i][j] = 0.f;
#pragma unroll 8
        for (int d = 0; d < DHEAD; d++) {
            float4 qv = *(const float4*)&Qs[d * QPAD + r0];
            float4 kv = *(const float4*)&Ks[d * QPAD + tx * 4];
            float qa[4] = {qv.x, qv.y, qv.z, qv.w};
            float ka[4] = {kv.x, kv.y, kv.z, kv.w};
#pragma unroll
            for (int i = 0; i < 4; i++)
#pragma unroll
                for (int j = 0; j < 4; j++)
                    sc[i][j] = fmaf(qa[i], ka[j], sc[i][j]);
        }
        const bool diag = (kb == qb);
#pragma unroll
        for (int i = 0; i < 4; i++)
#pragma unroll
            for (int j = 0; j < 4; j++) {
                float v = sc[i][j] * SCALE;
                if (diag && (kBase + tx * 4 + j) > (qBase + r0 + i)) v = neg_inf();
                Ps[(r0 + i) * QPAD + tx * 4 + j] = v;
            }
        __syncthreads();

        // online softmax (one thread per row)
        if (tid < 64) {
            int row = tid;
            float mp = rowm[row];
            float mx = mp;
#pragma unroll 8
            for (int c = 0; c < BK; c++) mx = fmaxf(mx, Ps[row * QPAD + c]);
            float corr = __expf(mp - mx);
            float sum = 0.f;
#pragma unroll 8
            for (int c = 0; c < BK; c++) {
                float p = __expf(Ps[row * QPAD + c] - mx);
                Ps[row * QPAD + c] = p;
                sum += p;
            }
            rowl[row]  = rowl[row] * corr + sum;
            rowm[row]  = mx;
            rowsc[row] = corr;
        }
        __syncthreads();

        // rescale running O, then O += P @ V
#pragma unroll
        for (int i = 0; i < 4; i++) {
            float cr = rowsc[r0 + i];
#pragma unroll
            for (int j = 0; j < 8; j++) o[i][j] *= cr;
        }
#pragma unroll 4
        for (int kk = 0; kk < BK; kk++) {
            float p[4];
#pragma unroll
            for (int i = 0; i < 4; i++) p[i] = Ps[(r0 + i) * QPAD + kk];
            float4 v0 = *(const float4*)&Vs[kk * 128 + tx * 4];
            float4 v1 = *(const float4*)&Vs[kk * 128 + 64 + tx * 4];
            float va[8] = {v0.x, v0.y, v0.z, v0.w, v1.x, v1.y, v1.z, v1.w};
#pragma unroll
            for (int i = 0; i < 4; i++)
#pragma unroll
                for (int j = 0; j < 8; j++)
                    o[i][j] = fmaf(p[i], va[j], o[i][j]);
        }
    }
    __syncthreads();

    // epilogue: normalize, write ctx [s*B+b, h*128 + c]
    const int b = bh >> 4;
    const int h = bh & 15;
#pragma unroll
    for (int i = 0; i < 4; i++) {
        float inv = 1.0f / rowl[r0 + i];
        int srow = qBase + r0 + i;
        float* dst = g_ctx + ((size_t)srow * B_SZ + b) * HIDN + h * DHEAD;
#pragma unroll
        for (int j = 0; j < 4; j++) dst[tx * 4 + j] = o[i][j] * inv;
#pragma unroll
        for (int j = 0; j < 4; j++) dst[64 + tx * 4 + j] = o[i][4 + j] * inv;
    }
}

// ============================================================================
// Kernel 3: dense GEMM  out[4096,2048] = ctx @ Wd  (skip_bias_add: no bias)
// ============================================================================
__global__ __launch_bounds__(256) void dense_gemm_kernel(
    const float* __restrict__ W, float* __restrict__ out)
{
    __shared__ float As[16][132];
    __shared__ float Bs[16][132];

    const int tid = threadIdx.x;
    const int rowBase = blockIdx.y * 128;
    const int colBase = blockIdx.x * 128;
    const int tx = tid & 15, ty = tid >> 4;

    float acc[8][8];
#pragma unroll
    for (int i = 0; i < 8; i++)
#pragma unroll
        for (int j = 0; j < 8; j++) acc[i][j] = 0.f;

    const int lrow = tid >> 2;
    const int lk   = (tid & 3) * 4;
    const int bkr  = tid >> 5;
    const int bcol = (tid & 31) * 4;

    for (int k0 = 0; k0 < HIDN; k0 += 16) {
#pragma unroll
        for (int h = 0; h < 2; h++) {
            int r = lrow + h * 64;
            float4 av = *(const float4*)(g_ctx + (size_t)(rowBase + r) * HIDN + k0 + lk);
            As[lk + 0][r] = av.x; As[lk + 1][r] = av.y;
            As[lk + 2][r] = av.z; As[lk + 3][r] = av.w;
        }
#pragma unroll
        for (int h = 0; h < 2; h++) {
            int kr = bkr + h * 8;
            float4 bv = *(const float4*)(W + (size_t)(k0 + kr) * HIDN + colBase + bcol);
            *(float4*)&Bs[kr][bcol] = bv;
        }
        __syncthreads();
#pragma unroll
        for (int kk = 0; kk < 16; kk++) {
            float4 a0 = *(const float4*)&As[kk][ty * 4];
            float4 a1 = *(const float4*)&As[kk][64 + ty * 4];
            float4 b0 = *(const float4*)&Bs[kk][tx * 4];
            float4 b1 = *(const float4*)&Bs[kk][64 + tx * 4];
            float ar[8] = {a0.x, a0.y, a0.z, a0.w, a1.x, a1.y, a1.z, a1.w};
            float br[8] = {b0.x, b0.y, b0.z, b0.w, b1.x, b1.y, b1.z, b1.w};
#pragma unroll
            for (int i = 0; i < 8; i++)
#pragma unroll
                for (int j = 0; j < 8; j++)
                    acc[i][j] = fmaf(ar[i], br[j], acc[i][j]);
        }
        __syncthreads();
    }

#pragma unroll
    for (int i = 0; i < 8; i++) {
        int r = rowBase + ((i < 4) ? (ty * 4 + i) : (64 + ty * 4 + i - 4));
#pragma unroll
        for (int j = 0; j < 8; j++) {
            int c = colBase + ((j < 4) ? (tx * 4 + j) : (64 + tx * 4 + j - 4));
            out[(size_t)r * HIDN + c] = acc[i][j];
        }
    }
}

// ============================================================================
// Kernel 4: bias tail  out[MROWS*HIDN + i] = b_dense[i]
// ============================================================================
__global__ void bias_tail_kernel(const float* __restrict__ bias,
                                 float* __restrict__ out, int n)
{
    int i = blockIdx.x * blockDim.x + threadIdx.x;
    if (i < n) out[(size_t)MROWS * HIDN + i] = bias[i];
}

// ============================================================================
extern "C" void kernel_launch(void* const* d_in, const int* in_sizes, int n_in,
                              void* d_out, int out_size)
{
    const float* hidden = (const float*)d_in[0];
    // d_in[1] = attention_mask (causal, deterministic) — applied analytically
    const float* Wqkv = (const float*)d_in[2];
    const float* bqkv = (const float*)d_in[3];
    const float* Wd   = (const float*)d_in[4];
    const float* bd   = (const float*)d_in[5];
    float* out = (float*)d_out;

    cudaFuncSetAttribute(attn_kernel,
                         cudaFuncAttributeMaxDynamicSharedMemorySize,
                         ATTN_SMEM_BYTES);

    qkv_gemm_kernel<<<dim3(QKVN / 128, MROWS / 128), 256>>>(hidden, Wqkv, bqkv);
    attn_kernel<<<dim3(S_LEN / BQ, B_SZ * NHEAD), 256, ATTN_SMEM_BYTES>>>();
    dense_gemm_kernel<<<dim3(HIDN / 128, MROWS / 128), 256>>>(Wd, out);

    int tail = out_size - MROWS * HIDN;
    if (tail > 0)
        bias_tail_kernel<<<(tail + 255) / 256, 256>>>(bd, out, tail);
}

// round 6
// speedup vs baseline: 1.4937x; 1.4937x over previous
#include <cuda_runtime.h>
#include <cuda_bf16.h>
#include <cstdint>

// ---------------- problem constants ----------------
#define S_LEN 2048
#define B_SZ  2
#define NHEAD 16
#define DHEAD 128
#define HIDN  2048
#define QKVN  6144
#define MROWS (S_LEN * B_SZ)     // 4096
#define SCALE 0.08838834764831845f

static __device__ __forceinline__ float neg_inf() { return __int_as_float(0xff800000); }

__device__ __forceinline__ uint32_t smem_u32(const void* p) {
    uint32_t a;
    asm("{ .reg .u64 t; cvta.to.shared.u64 t, %1; cvt.u32.u64 %0, t; }" : "=r"(a) : "l"(p));
    return a;
}

#define CP_ASYNC16(saddr, gptr) \
    asm volatile("cp.async.cg.shared.global [%0], [%1], 16;" :: "r"(saddr), "l"(gptr) : "memory")
#define CP_COMMIT() asm volatile("cp.async.commit_group;" ::: "memory")
#define CP_WAIT(n)  asm volatile("cp.async.wait_group %0;" :: "n"(n) : "memory")

#define LDSM4(r, addr) \
    asm volatile("ldmatrix.sync.aligned.m8n8.x4.shared.b16 {%0,%1,%2,%3}, [%4];" \
        : "=r"((r)[0]), "=r"((r)[1]), "=r"((r)[2]), "=r"((r)[3]) : "r"(addr))

#define MMA16816(d, a, b0v, b1v) \
    asm volatile("mma.sync.aligned.m16n8k16.row.col.f32.bf16.bf16.f32 " \
        "{%0,%1,%2,%3}, {%4,%5,%6,%7}, {%8,%9}, {%0,%1,%2,%3};" \
        : "+f"((d)[0]), "+f"((d)[1]), "+f"((d)[2]), "+f"((d)[3]) \
        : "r"((a)[0]), "r"((a)[1]), "r"((a)[2]), "r"((a)[3]), "r"(b0v), "r"(b1v))

// ---------------- scratch (static device globals; no allocations) ----------------
__device__ float g_q[(size_t)B_SZ * NHEAD * S_LEN * DHEAD];
__device__ float g_k[(size_t)B_SZ * NHEAD * S_LEN * DHEAD];
__device__ float g_v[(size_t)B_SZ * NHEAD * S_LEN * DHEAD];
__device__ float g_ctx[(size_t)MROWS * HIDN];

__device__ __nv_bfloat16 gAh[(size_t)MROWS * HIDN];      // hidden hi/lo
__device__ __nv_bfloat16 gAl[(size_t)MROWS * HIDN];
__device__ __nv_bfloat16 gBqh[(size_t)QKVN * HIDN];      // Wqkv^T [n][k] hi/lo
__device__ __nv_bfloat16 gBql[(size_t)QKVN * HIDN];
__device__ __nv_bfloat16 gBdh[(size_t)HIDN * HIDN];      // Wdense^T [n][k] hi/lo
__device__ __nv_bfloat16 gBdl[(size_t)HIDN * HIDN];
__device__ __nv_bfloat16 gCh[(size_t)MROWS * HIDN];      // ctx hi/lo
__device__ __nv_bfloat16 gCl[(size_t)MROWS * HIDN];

// ============================================================================
// Prep kernels
// ============================================================================
__global__ void cvt_split_kernel(const float* __restrict__ x,
                                 __nv_bfloat16* __restrict__ h,
                                 __nv_bfloat16* __restrict__ l, int n)
{
    int i = blockIdx.x * blockDim.x + threadIdx.x;
    if (i < n) {
        float v = x[i];
        __nv_bfloat16 hh = __float2bfloat16(v);
        h[i] = hh;
        l[i] = __float2bfloat16(v - __bfloat162float(hh));
    }
}

__global__ void transpose_split_kernel(const float* __restrict__ W,
                                       __nv_bfloat16* __restrict__ Th,
                                       __nv_bfloat16* __restrict__ Tl,
                                       int K, int N)
{
    __shared__ float t[32][33];
    int k0 = blockIdx.y * 32, n0 = blockIdx.x * 32;
    int tx = threadIdx.x, ty = threadIdx.y;
    for (int i = ty; i < 32; i += 8)
        t[i][tx] = W[(size_t)(k0 + i) * N + n0 + tx];
    __syncthreads();
    for (int i = ty; i < 32; i += 8) {
        float v = t[tx][i];               // = W[k0+tx][n0+i]
        __nv_bfloat16 h = __float2bfloat16(v);
        Th[(size_t)(n0 + i) * K + k0 + tx] = h;
        Tl[(size_t)(n0 + i) * K + k0 + tx] = __float2bfloat16(v - __bfloat162float(h));
    }
}

// ============================================================================
// HMMA GEMM core. C[128,128] tile, 256 threads (8 warps: 4M x 2N).
// K-chunks of 32, double-buffered cp.async, 80B-padded smem rows.
// ============================================================================
#define KC 32
#define NCHUNK (HIDN / KC)          // 64
#define ROW_B 80                    // 32 bf16 = 64B, padded to 80B (conflict-free ldmatrix)
#define TILE_B (128 * ROW_B)        // 10240
#define STAGE_B (4 * TILE_B)        // 40960 (Ah, Al, Bh, Bl)
#define GEMM_SMEM (2 * STAGE_B)     // 81920

#define GEMM_LOAD_STAGE(buf, k0, AhP, AlP, BhP, BlP)                               \
    {                                                                              \
        uint32_t stb = sb + (buf) * STAGE_B;                                       \
        _Pragma("unroll")                                                          \
        for (int t = 0; t < 8; t++) {                                              \
            int idx = tid + t * 256;                                               \
            int tile = idx >> 9;                                                   \
            int e = idx & 511;                                                     \
            int row = e >> 2, ch = e & 3;                                          \
            uint32_t sa = stb + tile * TILE_B + row * ROW_B + ch * 16;             \
            const __nv_bfloat16* gp;                                               \
            if (tile == 0)      gp = AhP + (size_t)(rowBase + row) * HIDN + (k0) + ch * 8; \
            else if (tile == 1) gp = AlP + (size_t)(rowBase + row) * HIDN + (k0) + ch * 8; \
            else if (tile == 2) gp = BhP + (size_t)(colBase + row) * HIDN + (k0) + ch * 8; \
            else                gp = BlP + (size_t)(colBase + row) * HIDN + (k0) + ch * 8; \
            CP_ASYNC16(sa, gp);                                                    \
        }                                                                          \
        CP_COMMIT();                                                               \
    }

#define GEMM_COMPUTE_STAGE(buf)                                                    \
    {                                                                              \
        uint32_t stb = sb + (buf) * STAGE_B;                                       \
        _Pragma("unroll")                                                          \
        for (int ks = 0; ks < 2; ks++) {                                           \
            uint32_t kb = ks * 32;                                                 \
            uint32_t ah[2][4], al[2][4];                                           \
            _Pragma("unroll")                                                      \
            for (int mi = 0; mi < 2; mi++) {                                       \
                uint32_t ra = (uint32_t)(m0 + mi * 16 + (lane & 15)) * ROW_B       \
                              + kb + (lane >> 4) * 16;                             \
                LDSM4(ah[mi], stb + 0 * TILE_B + ra);                              \
                LDSM4(al[mi], stb + 1 * TILE_B + ra);                              \
            }                                                                      \
            _Pragma("unroll")                                                      \
            for (int nb = 0; nb < 4; nb++) {                                       \
                uint32_t rb = (uint32_t)(n0 + nb * 16 + (lane & 7)                 \
                              + ((lane >> 4) & 1) * 8) * ROW_B                     \
                              + kb + ((lane >> 3) & 1) * 16;                       \
                uint32_t bh[4], bl[4];                                             \
                LDSM4(bh, stb + 2 * TILE_B + rb);                                  \
                LDSM4(bl, stb + 3 * TILE_B + rb);                                  \
                _Pragma("unroll")                                                  \
                for (int mi = 0; mi < 2; mi++) {                                   \
                    MMA16816(acc[mi][nb * 2 + 0], ah[mi], bh[0], bh[1]);           \
                    MMA16816(acc[mi][nb * 2 + 1], ah[mi], bh[2], bh[3]);           \
                    MMA16816(acc[mi][nb * 2 + 0], ah[mi], bl[0], bl[1]);           \
                    MMA16816(acc[mi][nb * 2 + 1], ah[mi], bl[2], bl[3]);           \
                    MMA16816(acc[mi][nb * 2 + 0], al[mi], bh[0], bh[1]);           \
                    MMA16816(acc[mi][nb * 2 + 1], al[mi], bh[2], bh[3]);           \
                }                                                                  \
            }                                                                      \
        }                                                                          \
    }

#define GEMM_MAINLOOP(AhP, AlP, BhP, BlP)                                          \
    extern __shared__ char smem[];                                                 \
    uint32_t sb = smem_u32(smem);                                                  \
    const int tid = threadIdx.x;                                                   \
    const int lane = tid & 31;                                                     \
    const int wrp = tid >> 5;                                                      \
    const int m0 = (wrp & 3) * 32;                                                 \
    const int n0 = (wrp >> 2) * 64;                                                \
    const int rowBase = blockIdx.y * 128;                                          \
    const int colBase = blockIdx.x * 128;                                          \
    float acc[2][8][4];                                                            \
    _Pragma("unroll")                                                              \
    for (int i = 0; i < 2; i++)                                                    \
        _Pragma("unroll")                                                          \
        for (int j = 0; j < 8; j++)                                                \
            _Pragma("unroll")                                                      \
            for (int r = 0; r < 4; r++) acc[i][j][r] = 0.f;                        \
    GEMM_LOAD_STAGE(0, 0, AhP, AlP, BhP, BlP)                                      \
    for (int c = 0; c < NCHUNK; c++) {                                             \
        if (c + 1 < NCHUNK) {                                                      \
            GEMM_LOAD_STAGE((c + 1) & 1, (c + 1) * KC, AhP, AlP, BhP, BlP)         \
            CP_WAIT(1);                                                            \
        } else {                                                                   \
            CP_WAIT(0);                                                            \
        }                                                                          \
        __syncthreads();                                                           \
        GEMM_COMPUTE_STAGE(c & 1)                                                  \
        __syncthreads();                                                           \
    }

// QKV GEMM: epilogue adds bias + scatters into g_q/g_k/g_v (Megatron layout)
__global__ __launch_bounds__(256) void qkv_mma_kernel(const float* __restrict__ bias)
{
    GEMM_MAINLOOP(gAh, gAl, gBqh, gBql)

#pragma unroll
    for (int nj = 0; nj < 8; nj++) {
        int c0 = colBase + n0 + nj * 8;           // 8-col group, same head/which
        int head  = c0 / 384;
        int jj0   = c0 - head * 384;
        int which = jj0 >> 7;
        int d0    = (jj0 & 127) + (lane & 3) * 2;
        float* dstBase = ((which == 0) ? g_q : (which == 1) ? g_k : g_v);
        int cc = c0 + (lane & 3) * 2;
        float b0v = bias[cc], b1v = bias[cc + 1];
#pragma unroll
        for (int mi = 0; mi < 2; mi++)
#pragma unroll
            for (int rp = 0; rp < 2; rp++) {
                int mrow = rowBase + m0 + mi * 16 + (lane >> 2) + rp * 8;
                int s = mrow >> 1, b = mrow & 1;
                float2 o;
                o.x = acc[mi][nj][rp * 2 + 0] + b0v;
                o.y = acc[mi][nj][rp * 2 + 1] + b1v;
                *(float2*)(dstBase + (((size_t)b * NHEAD + head) * S_LEN + s) * DHEAD + d0) = o;
            }
    }
}

// Dense GEMM: plain store
__global__ __launch_bounds__(256) void dense_mma_kernel(float* __restrict__ out)
{
    GEMM_MAINLOOP(gCh, gCl, gBdh, gBdl)

#pragma unroll
    for (int mi = 0; mi < 2; mi++)
#pragma unroll
        for (int rp = 0; rp < 2; rp++) {
            int mrow = rowBase + m0 + mi * 16 + (lane >> 2) + rp * 8;
            float* dstRow = out + (size_t)mrow * HIDN + colBase + n0;
#pragma unroll
            for (int nj = 0; nj < 8; nj++) {
                float2 o;
                o.x = acc[mi][nj][rp * 2 + 0];
                o.y = acc[mi][nj][rp * 2 + 1];
                *(float2*)(dstRow + nj * 8 + (lane & 3) * 2) = o;
            }
        }
}

// ============================================================================
// Flash-style causal attention (fp32 SIMT — proven correct, ~0.9ms)
// ============================================================================
#define BQ 64
#define BK 64
#define QPAD 68
#define ATTN_SMEM_BYTES ((2 * 128 * QPAD + 64 * 128 + 64 * QPAD + 3 * 64) * 4)

__global__ __launch_bounds__(256) void attn_kernel()
{
    extern __shared__ float sm[];
    float* Qs    = sm;
    float* Ks    = sm + 128 * QPAD;
    float* Vs    = sm + 2 * 128 * QPAD;
    float* Ps    = Vs + 64 * 128;
    float* rowm  = Ps + 64 * QPAD;
    float* rowl  = rowm + 64;
    float* rowsc = rowl + 64;

    const int tid = threadIdx.x;
    const int qb  = blockIdx.x;
    const int bh  = blockIdx.y;
    const int qBase = qb * BQ;
    const size_t base = (size_t)bh * S_LEN * DHEAD;

    const int tx = tid & 15;
    const int ty = tid >> 4;
    const int r0 = ty * 4;

    for (int f = tid; f < BQ * DHEAD / 4; f += 256) {
        int row = f >> 5;
        int d4  = (f & 31) * 4;
        float4 v = *(const float4*)(g_q + base + (size_t)(qBase + row) * DHEAD + d4);
        Qs[(d4 + 0) * QPAD + row] = v.x;
        Qs[(d4 + 1) * QPAD + row] = v.y;
        Qs[(d4 + 2) * QPAD + row] = v.z;
        Qs[(d4 + 3) * QPAD + row] = v.w;
    }
    if (tid < 64) { rowm[tid] = neg_inf(); rowl[tid] = 0.f; }

    float o[4][8];
#pragma unroll
    for (int i = 0; i < 4; i++)
#pragma unroll
        for (int j = 0; j < 8; j++) o[i][j] = 0.f;

    for (int kb = 0; kb <= qb; kb++) {
        const int kBase = kb * BK;
        __syncthreads();
        for (int f = tid; f < BK * DHEAD / 4; f += 256) {
            int row = f >> 5;
            int d4  = (f & 31) * 4;
            float4 kv = *(const float4*)(g_k + base + (size_t)(kBase + row) * DHEAD + d4);
            Ks[(d4 + 0) * QPAD + row] = kv.x;
            Ks[(d4 + 1) * QPAD + row] = kv.y;
            Ks[(d4 + 2) * QPAD + row] = kv.z;
            Ks[(d4 + 3) * QPAD + row] = kv.w;
            float4 vv = *(const float4*)(g_v + base + (size_t)(kBase + row) * DHEAD + d4);
            *(float4*)&Vs[row * 128 + d4] = vv;
        }
        __syncthreads();

        float sc[4][4];
#pragma unroll
        for (int i = 0; i < 4; i++)
#pragma unroll
            for (int j = 0; j < 4; j++) sc[i][j] = 0.f;
#pragma unroll 8
        for (int d = 0; d < DHEAD; d++) {
            float4 qv = *(const float4*)&Qs[d * QPAD + r0];
            float4 kv = *(const float4*)&Ks[d * QPAD + tx * 4];
            float qa[4] = {qv.x, qv.y, qv.z, qv.w};
            float ka[4] = {kv.x, kv.y, kv.z, kv.w};
#pragma unroll
            for (int i = 0; i < 4; i++)
#pragma unroll
                for (int j = 0; j < 4; j++)
                    sc[i][j] = fmaf(qa[i], ka[j], sc[i][j]);
        }
        const bool diag = (kb == qb);
#pragma unroll
        for (int i = 0; i < 4; i++)
#pragma unroll
            for (int j = 0; j < 4; j++) {
                float v = sc[i][j] * SCALE;
                if (diag && (kBase + tx * 4 + j) > (qBase + r0 + i)) v = neg_inf();
                Ps[(r0 + i) * QPAD + tx * 4 + j] = v;
            }
        __syncthreads();

        if (tid < 64) {
            int row = tid;
            float mp = rowm[row];
            float mx = mp;
#pragma unroll 8
            for (int c = 0; c < BK; c++) mx = fmaxf(mx, Ps[row * QPAD + c]);
            float corr = __expf(mp - mx);
            float sum = 0.f;
#pragma unroll 8
            for (int c = 0; c < BK; c++) {
                float p = __expf(Ps[row * QPAD + c] - mx);
                Ps[row * QPAD + c] = p;
                sum += p;
            }
            rowl[row]  = rowl[row] * corr + sum;
            rowm[row]  = mx;
            rowsc[row] = corr;
        }
        __syncthreads();

#pragma unroll
        for (int i = 0; i < 4; i++) {
            float cr = rowsc[r0 + i];
#pragma unroll
            for (int j = 0; j < 8; j++) o[i][j] *= cr;
        }
#pragma unroll 4
        for (int kk = 0; kk < BK; kk++) {
            float p[4];
#pragma unroll
            for (int i = 0; i < 4; i++) p[i] = Ps[(r0 + i) * QPAD + kk];
            float4 v0 = *(const float4*)&Vs[kk * 128 + tx * 4];
            float4 v1 = *(const float4*)&Vs[kk * 128 + 64 + tx * 4];
            float va[8] = {v0.x, v0.y, v0.z, v0.w, v1.x, v1.y, v1.z, v1.w};
#pragma unroll
            for (int i = 0; i < 4; i++)
#pragma unroll
                for (int j = 0; j < 8; j++)
                    o[i][j] = fmaf(p[i], va[j], o[i][j]);
        }
    }
    __syncthreads();

    const int b = bh >> 4;
    const int h = bh & 15;
#pragma unroll
    for (int i = 0; i < 4; i++) {
        float inv = 1.0f / rowl[r0 + i];
        int srow = qBase + r0 + i;
        float* dst = g_ctx + ((size_t)srow * B_SZ + b) * HIDN + h * DHEAD;
#pragma unroll
        for (int j = 0; j < 4; j++) dst[tx * 4 + j] = o[i][j] * inv;
#pragma unroll
        for (int j = 0; j < 4; j++) dst[64 + tx * 4 + j] = o[i][4 + j] * inv;
    }
}

// ============================================================================
// Bias tail
// ============================================================================
__global__ void bias_tail_kernel(const float* __restrict__ bias,
                                 float* __restrict__ out, int n)
{
    int i = blockIdx.x * blockDim.x + threadIdx.x;
    if (i < n) out[(size_t)MROWS * HIDN + i] = bias[i];
}

// ============================================================================
extern "C" void kernel_launch(void* const* d_in, const int* in_sizes, int n_in,
                              void* d_out, int out_size)
{
    const float* hidden = (const float*)d_in[0];
    const float* Wqkv = (const float*)d_in[2];
    const float* bqkv = (const float*)d_in[3];
    const float* Wd   = (const float*)d_in[4];
    const float* bd   = (const float*)d_in[5];
    float* out = (float*)d_out;

    cudaFuncSetAttribute(attn_kernel, cudaFuncAttributeMaxDynamicSharedMemorySize,
                         ATTN_SMEM_BYTES);
    cudaFuncSetAttribute(qkv_mma_kernel, cudaFuncAttributeMaxDynamicSharedMemorySize,
                         GEMM_SMEM);
    cudaFuncSetAttribute(dense_mma_kernel, cudaFuncAttributeMaxDynamicSharedMemorySize,
                         GEMM_SMEM);

    __nv_bfloat16 *dAh, *dAl, *dCh, *dCl, *dBqh, *dBql, *dBdh, *dBdl;
    cudaGetSymbolAddress((void**)&dAh, gAh);
    cudaGetSymbolAddress((void**)&dAl, gAl);
    cudaGetSymbolAddress((void**)&dCh, gCh);
    cudaGetSymbolAddress((void**)&dCl, gCl);
    cudaGetSymbolAddress((void**)&dBqh, gBqh);
    cudaGetSymbolAddress((void**)&dBql, gBql);
    cudaGetSymbolAddress((void**)&dBdh, gBdh);
    cudaGetSymbolAddress((void**)&dBdl, gBdl);
    float* dCtx;
    cudaGetSymbolAddress((void**)&dCtx, g_ctx);

    // prep: convert/transpose to bf16 hi/lo
    cvt_split_kernel<<<(MROWS * HIDN + 255) / 256, 256>>>(hidden, dAh, dAl, MROWS * HIDN);
    transpose_split_kernel<<<dim3(QKVN / 32, HIDN / 32), dim3(32, 8)>>>(Wqkv, dBqh, dBql, HIDN, QKVN);
    transpose_split_kernel<<<dim3(HIDN / 32, HIDN / 32), dim3(32, 8)>>>(Wd, dBdh, dBdl, HIDN, HIDN);

    // QKV projection (HMMA)
    qkv_mma_kernel<<<dim3(QKVN / 128, MROWS / 128), 256, GEMM_SMEM>>>(bqkv);

    // attention (fp32 SIMT)
    attn_kernel<<<dim3(S_LEN / BQ, B_SZ * NHEAD), 256, ATTN_SMEM_BYTES>>>();

    // ctx -> bf16 hi/lo, dense projection (HMMA)
    cvt_split_kernel<<<(MROWS * HIDN + 255) / 256, 256>>>(dCtx, dCh, dCl, MROWS * HIDN);
    dense_mma_kernel<<<dim3(HIDN / 128, MROWS / 128), 256, GEMM_SMEM>>>(out);

    int tail = out_size - MROWS * HIDN;
    if (tail > 0)
        bias_tail_kernel<<<(tail + 255) / 256, 256>>>(bd, out, tail);
}

// round 7
// speedup vs baseline: 2.6886x; 1.8000x over previous
#include <cuda_runtime.h>
#include <cuda_bf16.h>
#include <cstdint>

// ---------------- problem constants ----------------
#define S_LEN 2048
#define B_SZ  2
#define NHEAD 16
#define DHEAD 128
#define HIDN  2048
#define QKVN  6144
#define MROWS (S_LEN * B_SZ)     // 4096
#define SCALE 0.08838834764831845f
#define C2    0.12751743137316813f   // SCALE * log2(e)

static __device__ __forceinline__ float neg_inf() { return __int_as_float(0xff800000); }

__device__ __forceinline__ uint32_t smem_u32(const void* p) {
    uint32_t a;
    asm("{ .reg .u64 t; cvta.to.shared.u64 t, %1; cvt.u32.u64 %0, t; }" : "=r"(a) : "l"(p));
    return a;
}

#define CP_ASYNC16(saddr, gptr) \
    asm volatile("cp.async.cg.shared.global [%0], [%1], 16;" :: "r"(saddr), "l"(gptr) : "memory")
#define CP_COMMIT() asm volatile("cp.async.commit_group;" ::: "memory")
#define CP_WAIT(n)  asm volatile("cp.async.wait_group %0;" :: "n"(n) : "memory")

#define LDSM4(r, addr) \
    asm volatile("ldmatrix.sync.aligned.m8n8.x4.shared.b16 {%0,%1,%2,%3}, [%4];" \
        : "=r"((r)[0]), "=r"((r)[1]), "=r"((r)[2]), "=r"((r)[3]) : "r"(addr))
#define LDSM4T(r, addr) \
    asm volatile("ldmatrix.sync.aligned.m8n8.x4.trans.shared.b16 {%0,%1,%2,%3}, [%4];" \
        : "=r"((r)[0]), "=r"((r)[1]), "=r"((r)[2]), "=r"((r)[3]) : "r"(addr))

#define MMA16816(d, a, b0v, b1v) \
    asm volatile("mma.sync.aligned.m16n8k16.row.col.f32.bf16.bf16.f32 " \
        "{%0,%1,%2,%3}, {%4,%5,%6,%7}, {%8,%9}, {%0,%1,%2,%3};" \
        : "+f"((d)[0]), "+f"((d)[1]), "+f"((d)[2]), "+f"((d)[3]) \
        : "r"((a)[0]), "r"((a)[1]), "r"((a)[2]), "r"((a)[3]), "r"(b0v), "r"(b1v))

__device__ __forceinline__ uint32_t packbf(float lo, float hi) {
    __nv_bfloat162 t = __floats2bfloat162_rn(lo, hi);
    return *reinterpret_cast<uint32_t*>(&t);
}
__device__ __forceinline__ float quad_max(float v) {
    v = fmaxf(v, __shfl_xor_sync(0xffffffffu, v, 1));
    v = fmaxf(v, __shfl_xor_sync(0xffffffffu, v, 2));
    return v;
}
__device__ __forceinline__ float quad_sum(float v) {
    v += __shfl_xor_sync(0xffffffffu, v, 1);
    v += __shfl_xor_sync(0xffffffffu, v, 2);
    return v;
}

// ---------------- scratch (static device globals; no allocations) ----------------
__device__ __nv_bfloat16 g_qh[(size_t)B_SZ * NHEAD * S_LEN * DHEAD];
__device__ __nv_bfloat16 g_ql[(size_t)B_SZ * NHEAD * S_LEN * DHEAD];
__device__ __nv_bfloat16 g_kh[(size_t)B_SZ * NHEAD * S_LEN * DHEAD];
__device__ __nv_bfloat16 g_kl[(size_t)B_SZ * NHEAD * S_LEN * DHEAD];
__device__ __nv_bfloat16 g_vh[(size_t)B_SZ * NHEAD * S_LEN * DHEAD];
__device__ __nv_bfloat16 g_vl[(size_t)B_SZ * NHEAD * S_LEN * DHEAD];

__device__ __nv_bfloat16 gAh[(size_t)MROWS * HIDN];      // hidden hi/lo
__device__ __nv_bfloat16 gAl[(size_t)MROWS * HIDN];
__device__ __nv_bfloat16 gBqh[(size_t)QKVN * HIDN];      // Wqkv^T [n][k] hi/lo
__device__ __nv_bfloat16 gBql[(size_t)QKVN * HIDN];
__device__ __nv_bfloat16 gBdh[(size_t)HIDN * HIDN];      // Wdense^T [n][k] hi/lo
__device__ __nv_bfloat16 gBdl[(size_t)HIDN * HIDN];
__device__ __nv_bfloat16 gCh[(size_t)MROWS * HIDN];      // ctx hi/lo
__device__ __nv_bfloat16 gCl[(size_t)MROWS * HIDN];

// ============================================================================
// Prep kernels
// ============================================================================
__global__ void cvt_split_kernel(const float* __restrict__ x,
                                 __nv_bfloat16* __restrict__ h,
                                 __nv_bfloat16* __restrict__ l, int n)
{
    int i = blockIdx.x * blockDim.x + threadIdx.x;
    if (i < n) {
        float v = x[i];
        __nv_bfloat16 hh = __float2bfloat16(v);
        h[i] = hh;
        l[i] = __float2bfloat16(v - __bfloat162float(hh));
    }
}

__global__ void transpose_split_kernel(const float* __restrict__ W,
                                       __nv_bfloat16* __restrict__ Th,
                                       __nv_bfloat16* __restrict__ Tl,
                                       int K, int N)
{
    __shared__ float t[32][33];
    int k0 = blockIdx.y * 32, n0 = blockIdx.x * 32;
    int tx = threadIdx.x, ty = threadIdx.y;
    for (int i = ty; i < 32; i += 8)
        t[i][tx] = W[(size_t)(k0 + i) * N + n0 + tx];
    __syncthreads();
    for (int i = ty; i < 32; i += 8) {
        float v = t[tx][i];
        __nv_bfloat16 h = __float2bfloat16(v);
        Th[(size_t)(n0 + i) * K + k0 + tx] = h;
        Tl[(size_t)(n0 + i) * K + k0 + tx] = __float2bfloat16(v - __bfloat162float(h));
    }
}

// ============================================================================
// HMMA GEMM core (proven in R6). C[128,128] tile, 256 threads (8 warps 4Mx2N).
// ============================================================================
#define KC 32
#define NCHUNK (HIDN / KC)
#define ROW_B 80
#define TILE_B (128 * ROW_B)
#define STAGE_B (4 * TILE_B)
#define GEMM_SMEM (2 * STAGE_B)

#define GEMM_LOAD_STAGE(buf, k0, AhP, AlP, BhP, BlP)                               \
    {                                                                              \
        uint32_t stb = sb + (buf) * STAGE_B;                                       \
        _Pragma("unroll")                                                          \
        for (int t = 0; t < 8; t++) {                                              \
            int idx = tid + t * 256;                                               \
            int tile = idx >> 9;                                                   \
            int e = idx & 511;                                                     \
            int row = e >> 2, ch = e & 3;                                          \
            uint32_t sa = stb + tile * TILE_B + row * ROW_B + ch * 16;             \
            const __nv_bfloat16* gp;                                               \
            if (tile == 0)      gp = AhP + (size_t)(rowBase + row) * HIDN + (k0) + ch * 8; \
            else if (tile == 1) gp = AlP + (size_t)(rowBase + row) * HIDN + (k0) + ch * 8; \
            else if (tile == 2) gp = BhP + (size_t)(colBase + row) * HIDN + (k0) + ch * 8; \
            else                gp = BlP + (size_t)(colBase + row) * HIDN + (k0) + ch * 8; \
            CP_ASYNC16(sa, gp);                                                    \
        }                                                                          \
        CP_COMMIT();                                                               \
    }

#define GEMM_COMPUTE_STAGE(buf)                                                    \
    {                                                                              \
        uint32_t stb = sb + (buf) * STAGE_B;                                       \
        _Pragma("unroll")                                                          \
        for (int ks = 0; ks < 2; ks++) {                                           \
            uint32_t kb = ks * 32;                                                 \
            uint32_t ah[2][4], al[2][4];                                           \
            _Pragma("unroll")                                                      \
            for (int mi = 0; mi < 2; mi++) {                                       \
                uint32_t ra = (uint32_t)(m0 + mi * 16 + (lane & 15)) * ROW_B       \
                              + kb + (lane >> 4) * 16;                             \
                LDSM4(ah[mi], stb + 0 * TILE_B + ra);                              \
                LDSM4(al[mi], stb + 1 * TILE_B + ra);                              \
            }                                                                      \
            _Pragma("unroll")                                                      \
            for (int nb = 0; nb < 4; nb++) {                                       \
                uint32_t rb = (uint32_t)(n0 + nb * 16 + (lane & 7)                 \
                              + ((lane >> 4) & 1) * 8) * ROW_B                     \
                              + kb + ((lane >> 3) & 1) * 16;                       \
                uint32_t bh[4], bl[4];                                             \
                LDSM4(bh, stb + 2 * TILE_B + rb);                                  \
                LDSM4(bl, stb + 3 * TILE_B + rb);                                  \
                _Pragma("unroll")                                                  \
                for (int mi = 0; mi < 2; mi++) {                                   \
                    MMA16816(acc[mi][nb * 2 + 0], ah[mi], bh[0], bh[1]);           \
                    MMA16816(acc[mi][nb * 2 + 1], ah[mi], bh[2], bh[3]);           \
                    MMA16816(acc[mi][nb * 2 + 0], ah[mi], bl[0], bl[1]);           \
                    MMA16816(acc[mi][nb * 2 + 1], ah[mi], bl[2], bl[3]);           \
                    MMA16816(acc[mi][nb * 2 + 0], al[mi], bh[0], bh[1]);           \
                    MMA16816(acc[mi][nb * 2 + 1], al[mi], bh[2], bh[3]);           \
                }                                                                  \
            }                                                                      \
        }                                                                          \
    }

#define GEMM_MAINLOOP(AhP, AlP, BhP, BlP)                                          \
    extern __shared__ char smem[];                                                 \
    uint32_t sb = smem_u32(smem);                                                  \
    const int tid = threadIdx.x;                                                   \
    const int lane = tid & 31;                                                     \
    const int wrp = tid >> 5;                                                      \
    const int m0 = (wrp & 3) * 32;                                                 \
    const int n0 = (wrp >> 2) * 64;                                                \
    const int rowBase = blockIdx.y * 128;                                          \
    const int colBase = blockIdx.x * 128;                                          \
    float acc[2][8][4];                                                            \
    _Pragma("unroll")                                                              \
    for (int i = 0; i < 2; i++)                                                    \
        _Pragma("unroll")                                                          \
        for (int j = 0; j < 8; j++)                                                \
            _Pragma("unroll")                                                      \
            for (int r = 0; r < 4; r++) acc[i][j][r] = 0.f;                        \
    GEMM_LOAD_STAGE(0, 0, AhP, AlP, BhP, BlP)                                      \
    for (int c = 0; c < NCHUNK; c++) {                                             \
        if (c + 1 < NCHUNK) {                                                      \
            GEMM_LOAD_STAGE((c + 1) & 1, (c + 1) * KC, AhP, AlP, BhP, BlP)         \
            CP_WAIT(1);                                                            \
        } else {                                                                   \
            CP_WAIT(0);                                                            \
        }                                                                          \
        __syncthreads();                                                           \
        GEMM_COMPUTE_STAGE(c & 1)                                                  \
        __syncthreads();                                                           \
    }

// QKV GEMM: epilogue adds bias + writes bf16 hi/lo q/k/v (Megatron per-head layout)
__global__ __launch_bounds__(256) void qkv_mma_kernel(const float* __restrict__ bias)
{
    GEMM_MAINLOOP(gAh, gAl, gBqh, gBql)

#pragma unroll
    for (int nj = 0; nj < 8; nj++) {
        int c0 = colBase + n0 + nj * 8;
        int head  = c0 / 384;
        int jj0   = c0 - head * 384;
        int which = jj0 >> 7;
        int d0    = (jj0 & 127) + (lane & 3) * 2;
        __nv_bfloat16 *dH, *dL;
        if (which == 0)      { dH = g_qh; dL = g_ql; }
        else if (which == 1) { dH = g_kh; dL = g_kl; }
        else                 { dH = g_vh; dL = g_vl; }
        int cc = c0 + (lane & 3) * 2;
        float b0v = bias[cc], b1v = bias[cc + 1];
#pragma unroll
        for (int mi = 0; mi < 2; mi++)
#pragma unroll
            for (int rp = 0; rp < 2; rp++) {
                int mrow = rowBase + m0 + mi * 16 + (lane >> 2) + rp * 8;
                int s = mrow >> 1, b = mrow & 1;
                float v0 = acc[mi][nj][rp * 2 + 0] + b0v;
                float v1 = acc[mi][nj][rp * 2 + 1] + b1v;
                __nv_bfloat16 h0 = __float2bfloat16(v0);
                __nv_bfloat16 h1 = __float2bfloat16(v1);
                __nv_bfloat16 l0 = __float2bfloat16(v0 - __bfloat162float(h0));
                __nv_bfloat16 l1 = __float2bfloat16(v1 - __bfloat162float(h1));
                size_t off = (((size_t)b * NHEAD + head) * S_LEN + s) * DHEAD + d0;
                *(__nv_bfloat162*)(dH + off) = __halves2bfloat162(h0, h1);
                *(__nv_bfloat162*)(dL + off) = __halves2bfloat162(l0, l1);
            }
    }
}

// Dense GEMM: plain fp32 store
__global__ __launch_bounds__(256) void dense_mma_kernel(float* __restrict__ out)
{
    GEMM_MAINLOOP(gCh, gCl, gBdh, gBdl)

#pragma unroll
    for (int mi = 0; mi < 2; mi++)
#pragma unroll
        for (int rp = 0; rp < 2; rp++) {
            int mrow = rowBase + m0 + mi * 16 + (lane >> 2) + rp * 8;
            float* dstRow = out + (size_t)mrow * HIDN + colBase + n0;
#pragma unroll
            for (int nj = 0; nj < 8; nj++) {
                float2 o;
                o.x = acc[mi][nj][rp * 2 + 0];
                o.y = acc[mi][nj][rp * 2 + 1];
                *(float2*)(dstRow + nj * 8 + (lane & 3) * 2) = o;
            }
        }
}

// ============================================================================
// HMMA flash attention. Grid (16 qblocks, 32 bh), 256 threads (8 warps M-split).
// BQ=BK=128. Split-precision Q@K^T and P@V (3-pass each). ctx out = bf16 hi/lo.
// ============================================================================
#define AROW 272                       // 128 bf16 = 256B, padded to 272B
#define ATILE (128 * AROW)             // 34816
#define OFF_Q 0
#define OFF_K (2 * ATILE)
#define OFF_V (4 * ATILE)
#define ATTN_SMEM (6 * ATILE)          // 208896

#define LOAD_TILE(off, srcH, srcL, rowBase0)                                   \
    {                                                                          \
        _Pragma("unroll")                                                      \
        for (int t = 0; t < 16; t++) {                                         \
            int i = tid + t * 256;                                             \
            int hl = i >> 11;                                                  \
            int row = (i >> 4) & 127;                                          \
            int ch = i & 15;                                                   \
            const __nv_bfloat16* gp = (hl ? (srcL) : (srcH)) + base            \
                + (size_t)((rowBase0) + row) * DHEAD + ch * 8;                 \
            CP_ASYNC16(sb + (off) + hl * ATILE + row * AROW + ch * 16, gp);    \
        }                                                                      \
        CP_COMMIT();                                                           \
    }

__global__ __launch_bounds__(256) void attn_mma_kernel()
{
    extern __shared__ char smem[];
    uint32_t sb = smem_u32(smem);
    const int tid = threadIdx.x;
    const int lane = tid & 31;
    const int wrp = tid >> 5;
    const int qb = (int)gridDim.x - 1 - (int)blockIdx.x;   // big CTAs first
    const int bh = blockIdx.y;
    const int qBase = qb * 128;
    const size_t base = (size_t)bh * S_LEN * DHEAD;

    // prologue: Q, K0, V0
    LOAD_TILE(OFF_Q, g_qh, g_ql, qBase)
    LOAD_TILE(OFF_K, g_kh, g_kl, 0)
    LOAD_TILE(OFF_V, g_vh, g_vl, 0)

    float o[16][4];
#pragma unroll
    for (int i = 0; i < 16; i++)
#pragma unroll
        for (int j = 0; j < 4; j++) o[i][j] = 0.f;
    float rm0 = neg_inf(), rm1 = neg_inf(), rl0 = 0.f, rl1 = 0.f;
    const int r0 = lane >> 2;
    const int qRow0 = qBase + wrp * 16 + r0;

    for (int kb = 0; kb <= qb; kb++) {
        CP_WAIT(1);
        __syncthreads();

        // ---- S = Q @ K^T (3-pass split) ----
        float sc[16][4];
#pragma unroll
        for (int i = 0; i < 16; i++)
#pragma unroll
            for (int j = 0; j < 4; j++) sc[i][j] = 0.f;
#pragma unroll
        for (int ks = 0; ks < 8; ks++) {
            uint32_t ah[4], al[4];
            uint32_t ra = sb + OFF_Q + (uint32_t)(wrp * 16 + (lane & 15)) * AROW
                          + ks * 32 + (lane >> 4) * 16;
            LDSM4(ah, ra);
            LDSM4(al, ra + ATILE);
#pragma unroll
            for (int nb = 0; nb < 8; nb++) {
                uint32_t kh[4], kl[4];
                uint32_t rk = sb + OFF_K
                    + (uint32_t)(nb * 16 + (lane & 7) + ((lane >> 4) & 1) * 8) * AROW
                    + ks * 32 + ((lane >> 3) & 1) * 16;
                LDSM4(kh, rk);
                LDSM4(kl, rk + ATILE);
                MMA16816(sc[nb * 2 + 0], ah, kh[0], kh[1]);
                MMA16816(sc[nb * 2 + 1], ah, kh[2], kh[3]);
                MMA16816(sc[nb * 2 + 0], ah, kl[0], kl[1]);
                MMA16816(sc[nb * 2 + 1], ah, kl[2], kl[3]);
                MMA16816(sc[nb * 2 + 0], al, kh[0], kh[1]);
                MMA16816(sc[nb * 2 + 1], al, kh[2], kh[3]);
            }
        }
        __syncthreads();
        if (kb < qb) { LOAD_TILE(OFF_K, g_kh, g_kl, (kb + 1) * 128) }

        // ---- causal mask (diagonal block only) ----
        if (kb == qb) {
#pragma unroll
            for (int nb = 0; nb < 16; nb++)
#pragma unroll
                for (int c = 0; c < 4; c++) {
                    int col = qBase + nb * 8 + (lane & 3) * 2 + (c & 1);
                    int row = qRow0 + (c >> 1) * 8;
                    if (col > row) sc[nb][c] = neg_inf();
                }
        }

        // ---- online softmax bookkeeping ----
        float bm0 = neg_inf(), bm1 = neg_inf();
#pragma unroll
        for (int nb = 0; nb < 16; nb++) {
            bm0 = fmaxf(bm0, fmaxf(sc[nb][0], sc[nb][1]));
            bm1 = fmaxf(bm1, fmaxf(sc[nb][2], sc[nb][3]));
        }
        bm0 = quad_max(bm0);
        bm1 = quad_max(bm1);
        float nm0 = fmaxf(rm0, bm0), nm1 = fmaxf(rm1, bm1);
        float corr0 = exp2f((rm0 - nm0) * C2);
        float corr1 = exp2f((rm1 - nm1) * C2);
        rm0 = nm0; rm1 = nm1;
        rl0 *= corr0; rl1 *= corr1;
#pragma unroll
        for (int nb = 0; nb < 16; nb++) {
            o[nb][0] *= corr0; o[nb][1] *= corr0;
            o[nb][2] *= corr1; o[nb][3] *= corr1;
        }

        if (kb < qb) { CP_WAIT(1); } else { CP_WAIT(0); }
        __syncthreads();

        // ---- P = exp(S - m), split hi/lo, O += P @ V (3-pass split) ----
        float ps0 = 0.f, ps1 = 0.f;
#pragma unroll
        for (int ks = 0; ks < 8; ks++) {
            float phf[8], plf[8];
#pragma unroll
            for (int half = 0; half < 2; half++)
#pragma unroll
                for (int c = 0; c < 4; c++) {
                    float mr = (c < 2) ? nm0 : nm1;
                    float p = exp2f((sc[2 * ks + half][c] - mr) * C2);
                    if (c < 2) ps0 += p; else ps1 += p;
                    __nv_bfloat16 hb = __float2bfloat16(p);
                    float hf = __bfloat162float(hb);
                    phf[half * 4 + c] = hf;
                    plf[half * 4 + c] = p - hf;
                }
            uint32_t ph4[4], pl4[4];
            ph4[0] = packbf(phf[0], phf[1]); ph4[1] = packbf(phf[2], phf[3]);
            ph4[2] = packbf(phf[4], phf[5]); ph4[3] = packbf(phf[6], phf[7]);
            pl4[0] = packbf(plf[0], plf[1]); pl4[1] = packbf(plf[2], plf[3]);
            pl4[2] = packbf(plf[4], plf[5]); pl4[3] = packbf(plf[6], plf[7]);
#pragma unroll
            for (int nb = 0; nb < 8; nb++) {
                uint32_t vh[4], vl[4];
                uint32_t rv = sb + OFF_V
                    + (uint32_t)(ks * 16 + (lane & 7) + ((lane >> 3) & 1) * 8) * AROW
                    + nb * 32 + ((lane >> 4) & 1) * 16;
                LDSM4T(vh, rv);
                LDSM4T(vl, rv + ATILE);
                MMA16816(o[nb * 2 + 0], ph4, vh[0], vh[1]);
                MMA16816(o[nb * 2 + 1], ph4, vh[2], vh[3]);
                MMA16816(o[nb * 2 + 0], ph4, vl[0], vl[1]);
                MMA16816(o[nb * 2 + 1], ph4, vl[2], vl[3]);
                MMA16816(o[nb * 2 + 0], pl4, vh[0], vh[1]);
                MMA16816(o[nb * 2 + 1], pl4, vh[2], vh[3]);
            }
        }
        rl0 += ps0; rl1 += ps1;
        __syncthreads();
        if (kb < qb) { LOAD_TILE(OFF_V, g_vh, g_vl, (kb + 1) * 128) }
    }

    // ---- epilogue: normalize, write ctx hi/lo ----
    rl0 = quad_sum(rl0);
    rl1 = quad_sum(rl1);
    float inv0 = 1.f / rl0, inv1 = 1.f / rl1;
    const int b = bh >> 4, h = bh & 15;
#pragma unroll
    for (int nb = 0; nb < 16; nb++) {
        int col = h * DHEAD + nb * 8 + (lane & 3) * 2;
        float v00 = o[nb][0] * inv0, v01 = o[nb][1] * inv0;
        float v10 = o[nb][2] * inv1, v11 = o[nb][3] * inv1;
        __nv_bfloat16 h00 = __float2bfloat16(v00), h01 = __float2bfloat16(v01);
        __nv_bfloat16 h10 = __float2bfloat16(v10), h11 = __float2bfloat16(v11);
        __nv_bfloat16 l00 = __float2bfloat16(v00 - __bfloat162float(h00));
        __nv_bfloat16 l01 = __float2bfloat16(v01 - __bfloat162float(h01));
        __nv_bfloat16 l10 = __float2bfloat16(v10 - __bfloat162float(h10));
        __nv_bfloat16 l11 = __float2bfloat16(v11 - __bfloat162float(h11));
        size_t off0 = ((size_t)qRow0 * B_SZ + b) * HIDN + col;
        size_t off1 = ((size_t)(qRow0 + 8) * B_SZ + b) * HIDN + col;
        *(__nv_bfloat162*)(gCh + off0) = __halves2bfloat162(h00, h01);
        *(__nv_bfloat162*)(gCl + off0) = __halves2bfloat162(l00, l01);
        *(__nv_bfloat162*)(gCh + off1) = __halves2bfloat162(h10, h11);
        *(__nv_bfloat162*)(gCl + off1) = __halves2bfloat162(l10, l11);
    }
}

// ============================================================================
// Bias tail
// ============================================================================
__global__ void bias_tail_kernel(const float* __restrict__ bias,
                                 float* __restrict__ out, int n)
{
    int i = blockIdx.x * blockDim.x + threadIdx.x;
    if (i < n) out[(size_t)MROWS * HIDN + i] = bias[i];
}

// ============================================================================
extern "C" void kernel_launch(void* const* d_in, const int* in_sizes, int n_in,
                              void* d_out, int out_size)
{
    const float* hidden = (const float*)d_in[0];
    const float* Wqkv = (const float*)d_in[2];
    const float* bqkv = (const float*)d_in[3];
    const float* Wd   = (const float*)d_in[4];
    const float* bd   = (const float*)d_in[5];
    float* out = (float*)d_out;

    cudaFuncSetAttribute(qkv_mma_kernel, cudaFuncAttributeMaxDynamicSharedMemorySize,
                         GEMM_SMEM);
    cudaFuncSetAttribute(dense_mma_kernel, cudaFuncAttributeMaxDynamicSharedMemorySize,
                         GEMM_SMEM);
    cudaFuncSetAttribute(attn_mma_kernel, cudaFuncAttributeMaxDynamicSharedMemorySize,
                         ATTN_SMEM);

    __nv_bfloat16 *dAh, *dAl, *dBqh, *dBql, *dBdh, *dBdl;
    cudaGetSymbolAddress((void**)&dAh, gAh);
    cudaGetSymbolAddress((void**)&dAl, gAl);
    cudaGetSymbolAddress((void**)&dBqh, gBqh);
    cudaGetSymbolAddress((void**)&dBql, gBql);
    cudaGetSymbolAddress((void**)&dBdh, gBdh);
    cudaGetSymbolAddress((void**)&dBdl, gBdl);

    // prep: convert/transpose to bf16 hi/lo
    cvt_split_kernel<<<(MROWS * HIDN + 255) / 256, 256>>>(hidden, dAh, dAl, MROWS * HIDN);
    transpose_split_kernel<<<dim3(QKVN / 32, HIDN / 32), dim3(32, 8)>>>(Wqkv, dBqh, dBql, HIDN, QKVN);
    transpose_split_kernel<<<dim3(HIDN / 32, HIDN / 32), dim3(32, 8)>>>(Wd, dBdh, dBdl, HIDN, HIDN);

    // QKV projection (HMMA) -> bf16 hi/lo q/k/v
    qkv_mma_kernel<<<dim3(QKVN / 128, MROWS / 128), 256, GEMM_SMEM>>>(bqkv);

    // flash attention (HMMA) -> bf16 hi/lo ctx
    attn_mma_kernel<<<dim3(S_LEN / 128, B_SZ * NHEAD), 256, ATTN_SMEM>>>();

    // dense projection (HMMA)
    dense_mma_kernel<<<dim3(HIDN / 128, MROWS / 128), 256, GEMM_SMEM>>>(out);

    int tail = out_size - MROWS * HIDN;
    if (tail > 0)
        bias_tail_kernel<<<(tail + 255) / 256, 256>>>(bd, out, tail);
}